// round 9
// baseline (speedup 1.0000x reference)
#include <cuda_runtime.h>
#include <cuda_bf16.h>

#define PL_TOTAL (2048 * 256)   // 524288 occurrences
#define NNODES   50000
#define DIM      256

// Scratch (static device globals -- no allocation in kernel_launch)
__device__ __align__(32) float g_q[(size_t)NNODES * DIM];
__device__ __align__(16) float g_agg[(size_t)NNODES * DIM];
__device__ float g_denom[NNODES];
__device__ int   g_hist[NNODES];
__device__ int   g_start[NNODES];
__device__ int   g_cursor[NNODES];
__device__ int   g_sorted[PL_TOTAL];
__device__ int   g_mask_word;   // 1 = mask elements are 4-byte (f32/i32), 0 = 1-byte

__device__ __forceinline__ bool is_live(const void* mask, int occ) {
    return g_mask_word ? (((const unsigned*)mask)[occ] != 0u)
                       : (((const unsigned char*)mask)[occ] != 0);
}

// ---------------------------------------------------------------------------
// Detect mask element width from raw bytes (deterministic).
// ---------------------------------------------------------------------------
__global__ void detect_mask_kernel(const unsigned char* __restrict__ m) {
    __shared__ int f32flag, oddflag;
    if (threadIdx.x == 0) { f32flag = 0; oddflag = 0; }
    __syncthreads();
    for (int i = threadIdx.x; i < 4096; i += blockDim.x) {
        unsigned char b = m[i];
        if (b == 0x3F && (i & 3) == 3) atomicOr(&f32flag, 1);
        if (b != 0 && (i & 3) != 0)    atomicOr(&oddflag, 1);
    }
    __syncthreads();
    if (threadIdx.x == 0)
        g_mask_word = (f32flag || !oddflag) ? 1 : 0;
}

// ---------------------------------------------------------------------------
// Counting sort of live occurrences by node: hist -> scan -> fill
// ---------------------------------------------------------------------------
__global__ void zero_hist_kernel() {
    int i = blockIdx.x * blockDim.x + threadIdx.x;
    if (i < NNODES) g_hist[i] = 0;
}

__global__ __launch_bounds__(256)
void hist_kernel(const void* __restrict__ mask, const int* __restrict__ idx) {
    int occ = blockIdx.x * blockDim.x + threadIdx.x;
    if (occ >= PL_TOTAL) return;
    if (!is_live(mask, occ)) return;
    atomicAdd(&g_hist[idx[occ]], 1);
}

__global__ __launch_bounds__(1024)
void scan_kernel() {
    __shared__ int psum[1024];
    const int t = threadIdx.x;
    const int lo = t * 49;
    const int hi = min(lo + 49, NNODES);
    int s = 0;
    for (int i = lo; i < hi; i++) s += g_hist[i];
    psum[t] = s;
    __syncthreads();
    for (int d = 1; d < 1024; d <<= 1) {
        int v = (t >= d) ? psum[t - d] : 0;
        __syncthreads();
        psum[t] += v;
        __syncthreads();
    }
    int run = (t == 0) ? 0 : psum[t - 1];
    for (int i = lo; i < hi; i++) {
        g_start[i]  = run;
        g_cursor[i] = run;
        run += g_hist[i];
    }
}

__global__ __launch_bounds__(256)
void fill_kernel(const void* __restrict__ mask, const int* __restrict__ idx) {
    int occ = blockIdx.x * blockDim.x + threadIdx.x;
    if (occ >= PL_TOTAL) return;
    if (!is_live(mask, occ)) return;
    int pos = atomicAdd(&g_cursor[idx[occ]], 1);
    g_sorted[pos] = occ;
}

// ---------------------------------------------------------------------------
// Binned aggregation, 8-lane-group SIMD: one warp per node, warp split into
// 4 groups of 8 lanes; each group processes a DIFFERENT occurrence per
// iteration (4 in flight via lanes, not registers). Per lane: 32-float slice,
// 8 independent LDG.128 (MLP=8), 3-stage in-group shfl reduce. Cross-group
// accumulator merge once at the end. No atomics.
// ---------------------------------------------------------------------------
__device__ __forceinline__ float4 ldcs4(const float* p) {
    float4 v;
    asm volatile("ld.global.cs.v4.f32 {%0,%1,%2,%3}, [%4];"
                 : "=f"(v.x), "=f"(v.y), "=f"(v.z), "=f"(v.w) : "l"(p));
    return v;
}

__global__ __launch_bounds__(256)
void agg_kernel(const float* __restrict__ enc) {
    int node = (int)((blockIdx.x * blockDim.x + threadIdx.x) >> 5);
    int lane = threadIdx.x & 31;
    if (node >= NNODES) return;

    const int grp = lane >> 3;        // 0..3 (occurrence slot in iteration)
    const int gl  = lane & 7;         // 0..7 (lane within group)
    const int start = g_start[node];
    const int cnt   = g_hist[node];

    // q slice: dims [gl*32, gl*32+32)
    const float4* qp = (const float4*)(g_q + (size_t)node * DIM + gl * 32);
    float4 q[8];
#pragma unroll
    for (int j = 0; j < 8; j++) q[j] = qp[j];

    float4 acc[8];
#pragma unroll
    for (int j = 0; j < 8; j++) acc[j] = make_float4(0.f, 0.f, 0.f, 0.f);
    float den = 0.0f;

    for (int i = 0; i < cnt; i += 4) {
        int ii = i + grp;
        bool act = (ii < cnt);
        int occ = g_sorted[start + (act ? ii : cnt - 1)];
        const float* p = enc + (size_t)occ * DIM + gl * 32;

        float4 e[8];
#pragma unroll
        for (int j = 0; j < 8; j++) e[j] = ldcs4(p + j * 4);

        float d = 0.0f;
#pragma unroll
        for (int j = 0; j < 8; j++)
            d += e[j].x * q[j].x + e[j].y * q[j].y
               + e[j].z * q[j].z + e[j].w * q[j].w;
        // reduce within the 8-lane group (xor masks stay inside group)
        d += __shfl_xor_sync(0xffffffffu, d, 4);
        d += __shfl_xor_sync(0xffffffffu, d, 2);
        d += __shfl_xor_sync(0xffffffffu, d, 1);

        float w = act ? __expf(d * 0.0625f) : 0.0f;   // 1/sqrt(256)

#pragma unroll
        for (int j = 0; j < 8; j++) {
            acc[j].x += w * e[j].x; acc[j].y += w * e[j].y;
            acc[j].z += w * e[j].z; acc[j].w += w * e[j].w;
        }
        den += w;
    }

    // merge the 4 group-partial accumulators (lanes with equal gl)
#pragma unroll
    for (int o = 8; o <= 16; o <<= 1) {
#pragma unroll
        for (int j = 0; j < 8; j++) {
            acc[j].x += __shfl_xor_sync(0xffffffffu, acc[j].x, o);
            acc[j].y += __shfl_xor_sync(0xffffffffu, acc[j].y, o);
            acc[j].z += __shfl_xor_sync(0xffffffffu, acc[j].z, o);
            acc[j].w += __shfl_xor_sync(0xffffffffu, acc[j].w, o);
        }
        den += __shfl_xor_sync(0xffffffffu, den, o);
    }

    if (grp == 0) {
        float4* op = (float4*)(g_agg + (size_t)node * DIM + gl * 32);
#pragma unroll
        for (int j = 0; j < 8; j++) op[j] = acc[j];
        if (gl == 0) g_denom[node] = den;
    }
}

// ---------------------------------------------------------------------------
// TF32 tensor-core GEMM with fragment-swizzled SMEM (vector LDS).
//   MODE 0: KTOT=256, C = fp32 q projection.
//   MODE 1: KTOT=512, A2 scaled by 1/(denom+1e-9) on load, fused gate epilogue.
// Block tile 128x128, K-chunk 32, 256 threads = 8 warps (4M x 2N),
// warp tile 32x64 = 2x8 m16n8k8 mma tiles.
// ---------------------------------------------------------------------------
__device__ __forceinline__ unsigned cvt_tf32(float x) {
    unsigned u;
    asm("cvt.rna.tf32.f32 %0, %1;" : "=r"(u) : "f"(x));
    return u;
}

template <int KTOT, int MODE>
__global__ __launch_bounds__(256, 2)
void tf32_gemm_kernel(const float* __restrict__ A1,
                      const float* __restrict__ A2,
                      const float* __restrict__ W,
                      const float* __restrict__ bias,
                      float* __restrict__ Cout,
                      int M) {
    __shared__ uint4 AsF[8][4][33];
    __shared__ uint2 BsF[4][16][33];

    const int tid  = threadIdx.x;
    const int bm   = blockIdx.x * 128;
    const int bn   = blockIdx.y * 128;
    const int warp = tid >> 5;
    const int lane = tid & 31;
    const int g0   = (warp & 3) * 2;
    const int n80  = (warp >> 2) * 8;
    const int kq   = lane & 3;
    const int r    = lane >> 2;

    float c[2][8][4];
#pragma unroll
    for (int i = 0; i < 2; i++)
#pragma unroll
        for (int j = 0; j < 8; j++)
#pragma unroll
            for (int t = 0; t < 4; t++) c[i][j][t] = 0.0f;

    for (int k0 = 0; k0 < KTOT; k0 += 32) {
        const bool isA2 = (KTOT == 512) && (k0 >= 256);
        const float* Asrc = isA2 ? A2 : A1;
        const int kloc = k0 & 255;

#pragma unroll
        for (int j = 0; j < 4; j++) {
            int i = tid + j * 256;
            int row = i >> 3;
            int c4  = i & 7;
            int grow = bm + row; if (grow >= M) grow = M - 1;
            float4 v = *(const float4*)(Asrc + (size_t)grow * 256 + kloc + c4 * 4);
            if (MODE == 1 && isA2) {
                float rd = 1.0f / (g_denom[grow] + 1e-9f);
                v.x *= rd; v.y *= rd; v.z *= rd; v.w *= rd;
            }
            int gg = row >> 4, h = (row >> 3) & 1, rr = row & 7;
            int kk = c4 >> 1, half = c4 & 1;
            unsigned* dst = (unsigned*)&AsF[gg][kk][0];
            int base = rr * 16 + half * 2 + h;
            dst[base]      = cvt_tf32(v.x);
            dst[base + 4]  = cvt_tf32(v.y);
            dst[base + 8]  = cvt_tf32(v.z);
            dst[base + 12] = cvt_tf32(v.w);
        }
#pragma unroll
        for (int j = 0; j < 4; j++) {
            int i = tid + j * 256;
            int krow = i >> 5;
            int c4   = i & 31;
            float4 v = *(const float4*)(W + (size_t)(k0 + krow) * 256 + bn + c4 * 4);
            int kk = krow >> 3, kqw = krow & 3, half = (krow >> 2) & 1;
            int n8 = c4 >> 1, rb = (c4 & 1) * 4;
            unsigned* dst = (unsigned*)&BsF[kk][n8][0];
            int base = (rb * 4 + kqw) * 2 + half;
            dst[base]      = cvt_tf32(v.x);
            dst[base + 8]  = cvt_tf32(v.y);
            dst[base + 16] = cvt_tf32(v.z);
            dst[base + 24] = cvt_tf32(v.w);
        }
        __syncthreads();

#pragma unroll
        for (int kk = 0; kk < 4; kk++) {
            uint4 af[2];
            af[0] = AsF[g0][kk][lane];
            af[1] = AsF[g0 + 1][kk][lane];
            uint2 bf[8];
#pragma unroll
            for (int nt = 0; nt < 8; nt++) bf[nt] = BsF[kk][n80 + nt][lane];
#pragma unroll
            for (int mt = 0; mt < 2; mt++)
#pragma unroll
                for (int nt = 0; nt < 8; nt++) {
                    asm volatile(
                        "mma.sync.aligned.m16n8k8.row.col.f32.tf32.tf32.f32 "
                        "{%0,%1,%2,%3}, {%4,%5,%6,%7}, {%8,%9}, {%0,%1,%2,%3};"
                        : "+f"(c[mt][nt][0]), "+f"(c[mt][nt][1]),
                          "+f"(c[mt][nt][2]), "+f"(c[mt][nt][3])
                        : "r"(af[mt].x), "r"(af[mt].y), "r"(af[mt].z), "r"(af[mt].w),
                          "r"(bf[nt].x), "r"(bf[nt].y));
                }
        }
        __syncthreads();
    }

    const int wm = (warp & 3) * 32;
    const int wn = (warp >> 2) * 64;
#pragma unroll
    for (int mt = 0; mt < 2; mt++) {
#pragma unroll
        for (int h = 0; h < 2; h++) {
            int m = bm + wm + mt * 16 + r + h * 8;
            if (m >= M) continue;
            float rdm = 0.0f;
            if (MODE == 1) rdm = 1.0f / (g_denom[m] + 1e-9f);
#pragma unroll
            for (int nt = 0; nt < 8; nt++) {
                int n = bn + wn + nt * 8 + 2 * kq;
                float v0 = c[mt][nt][h * 2 + 0];
                float v1 = c[mt][nt][h * 2 + 1];
                if (MODE == 0) {
                    *(float2*)(Cout + (size_t)m * 256 + n) = make_float2(v0, v1);
                } else {
                    float2 bb = *(const float2*)(bias + n);
                    float2 pv = *(const float2*)(A1 + (size_t)m * 256 + n);
                    float2 ag = *(const float2*)(A2 + (size_t)m * 256 + n);
                    ag.x *= rdm; ag.y *= rdm;
                    float z0 = 1.0f / (1.0f + __expf(-(v0 + bb.x)));
                    float z1 = 1.0f / (1.0f + __expf(-(v1 + bb.y)));
                    float2 o;
                    o.x = z0 * pv.x + (1.0f - z0) * ag.x;
                    o.y = z1 * pv.y + (1.0f - z1) * ag.y;
                    *(float2*)(Cout + (size_t)m * 256 + n) = o;
                }
            }
        }
    }
}

// ---------------------------------------------------------------------------
// Launch
// Inputs: 0 encoded_paths f32 [2048,256,256], 1 paths_mask (autodetected),
// 2 paths_node_indices i32, 3 previous_encodings f32 [50000,256],
// 4 Wq f32 [256,256], 5 Wg f32 [512,256], 6 bg f32 [256], 7 nr_cfg_nodes
// ---------------------------------------------------------------------------
extern "C" void kernel_launch(void* const* d_in, const int* in_sizes, int n_in,
                              void* d_out, int out_size) {
    const float* enc  = (const float*)d_in[0];
    const void*  mask = d_in[1];
    const int*   idx  = (const int*)d_in[2];
    const float* prev = (const float*)d_in[3];
    const float* Wq   = (const float*)d_in[4];
    const float* Wg   = (const float*)d_in[5];
    const float* bg   = (const float*)d_in[6];
    float* out        = (float*)d_out;

    void *qp = nullptr, *aggp = nullptr;
    cudaGetSymbolAddress(&qp, g_q);
    cudaGetSymbolAddress(&aggp, g_agg);
    float* q_buf   = (float*)qp;
    float* agg_buf = (float*)aggp;

    const int M = NNODES;
    dim3 grid((M + 127) / 128, 2);

    // 0) detect mask element width; zero histogram
    detect_mask_kernel<<<1, 256>>>((const unsigned char*)mask);
    zero_hist_kernel<<<(NNODES + 255) / 256, 256>>>();

    // 1) q = prev @ Wq  (tf32 tensor cores)
    tf32_gemm_kernel<256, 0><<<grid, 256>>>(prev, prev, Wq, nullptr, q_buf, M);

    // 2) counting sort of live occurrences by node
    hist_kernel<<<PL_TOTAL / 256, 256>>>(mask, idx);
    scan_kernel<<<1, 1024>>>();
    fill_kernel<<<PL_TOTAL / 256, 256>>>(mask, idx);

    // 3) binned aggregation (one warp per node, 4 groups of 8 lanes, no atomics)
    agg_kernel<<<(NNODES * 32 + 255) / 256, 256>>>(enc);

    // 4) fused: out = z*prev + (1-z)*(agg/denom), z = sigmoid([prev|agg/denom]@Wg+bg)
    tf32_gemm_kernel<512, 1><<<grid, 256>>>(prev, agg_buf, Wg, bg, out, M);
}

// round 10
// speedup vs baseline: 1.1945x; 1.1945x over previous
#include <cuda_runtime.h>
#include <cuda_bf16.h>

#define PL_TOTAL (2048 * 256)   // 524288 occurrences
#define NNODES   50000
#define DIM      256

// Scratch (static device globals -- no allocation in kernel_launch)
__device__ __align__(32) float g_q[(size_t)NNODES * DIM];
__device__ __align__(16) float g_agg[(size_t)NNODES * DIM];
__device__ float g_denom[NNODES];
__device__ int   g_hist[NNODES];
__device__ int   g_start[NNODES];
__device__ int   g_cursor[NNODES];
__device__ int   g_sorted[PL_TOTAL];
__device__ int   g_mask_word;   // 1 = mask elements are 4-byte (f32/i32), 0 = 1-byte

__device__ __forceinline__ bool is_live(const void* mask, int occ) {
    return g_mask_word ? (((const unsigned*)mask)[occ] != 0u)
                       : (((const unsigned char*)mask)[occ] != 0);
}

// ---------------------------------------------------------------------------
// Detect mask element width from raw bytes (deterministic).
// ---------------------------------------------------------------------------
__global__ void detect_mask_kernel(const unsigned char* __restrict__ m) {
    __shared__ int f32flag, oddflag;
    if (threadIdx.x == 0) { f32flag = 0; oddflag = 0; }
    __syncthreads();
    for (int i = threadIdx.x; i < 4096; i += blockDim.x) {
        unsigned char b = m[i];
        if (b == 0x3F && (i & 3) == 3) atomicOr(&f32flag, 1);
        if (b != 0 && (i & 3) != 0)    atomicOr(&oddflag, 1);
    }
    __syncthreads();
    if (threadIdx.x == 0)
        g_mask_word = (f32flag || !oddflag) ? 1 : 0;
}

// ---------------------------------------------------------------------------
// Counting sort of live occurrences by node: hist -> scan -> fill
// ---------------------------------------------------------------------------
__global__ void zero_hist_kernel() {
    int i = blockIdx.x * blockDim.x + threadIdx.x;
    if (i < NNODES) g_hist[i] = 0;
}

__global__ __launch_bounds__(256)
void hist_kernel(const void* __restrict__ mask, const int* __restrict__ idx) {
    int occ = blockIdx.x * blockDim.x + threadIdx.x;
    if (occ >= PL_TOTAL) return;
    if (!is_live(mask, occ)) return;
    atomicAdd(&g_hist[idx[occ]], 1);
}

__global__ __launch_bounds__(1024)
void scan_kernel() {
    __shared__ int psum[1024];
    const int t = threadIdx.x;
    const int lo = t * 49;
    const int hi = min(lo + 49, NNODES);
    int s = 0;
    for (int i = lo; i < hi; i++) s += g_hist[i];
    psum[t] = s;
    __syncthreads();
    for (int d = 1; d < 1024; d <<= 1) {
        int v = (t >= d) ? psum[t - d] : 0;
        __syncthreads();
        psum[t] += v;
        __syncthreads();
    }
    int run = (t == 0) ? 0 : psum[t - 1];
    for (int i = lo; i < hi; i++) {
        g_start[i]  = run;
        g_cursor[i] = run;
        run += g_hist[i];
    }
}

__global__ __launch_bounds__(256)
void fill_kernel(const void* __restrict__ mask, const int* __restrict__ idx) {
    int occ = blockIdx.x * blockDim.x + threadIdx.x;
    if (occ >= PL_TOTAL) return;
    if (!is_live(mask, occ)) return;
    int pos = atomicAdd(&g_cursor[idx[occ]], 1);
    g_sorted[pos] = occ;
}

// ---------------------------------------------------------------------------
// Binned aggregation, 2-wide ILP + index software pipeline: one warp per
// node. The indices for pair (i+4) are fetched in iteration i, so the enc
// loads for pair (i+2) use indices already resident in registers -- the
// idx->LDG dependency never stalls the enc prefetch. No atomics.
// ---------------------------------------------------------------------------
__device__ __forceinline__ float4 ldcs4(const float* p) {
    float4 v;
    asm volatile("ld.global.cs.v4.f32 {%0,%1,%2,%3}, [%4];"
                 : "=f"(v.x), "=f"(v.y), "=f"(v.z), "=f"(v.w) : "l"(p));
    return v;
}

__global__ __launch_bounds__(256)
void agg_kernel(const float* __restrict__ enc) {
    int node = (int)((blockIdx.x * blockDim.x + threadIdx.x) >> 5);
    int lane = threadIdx.x & 31;
    if (node >= NNODES) return;

    const int start = g_start[node];
    const int cnt   = g_hist[node];

    const float* qp = g_q + (size_t)node * DIM + lane * 8;
    float4 q0 = *(const float4*)qp;
    float4 q1 = *(const float4*)(qp + 4);

    float4 a0 = make_float4(0.f, 0.f, 0.f, 0.f);
    float4 a1 = make_float4(0.f, 0.f, 0.f, 0.f);
    float den = 0.0f;

    if (cnt > 0) {
        // pair 0 data loads (indices straight from memory, once)
        int o0 = g_sorted[start];
        int o1 = g_sorted[start + ((cnt > 1) ? 1 : 0)];
        const float* p0 = enc + (size_t)o0 * DIM + lane * 8;
        const float* p1 = enc + (size_t)o1 * DIM + lane * 8;
        float4 e0 = ldcs4(p0), e1 = ldcs4(p0 + 4);
        float4 f0 = ldcs4(p1), f1 = ldcs4(p1 + 4);

        // indices for pair 1 (i = 2, 3), fetched with a full iteration of lead
        int j0 = 0, j1 = 0;
        if (cnt > 2) {
            j0 = g_sorted[start + 2];
            j1 = g_sorted[start + ((cnt > 3) ? 3 : 2)];
        }

        for (int i = 0; i < cnt; i += 2) {
            float4 ge0 = e0, ge1 = e1, gf0 = f0, gf1 = f1;

            // issue enc loads for pair (i+2) -- indices already in registers
            if (i + 2 < cnt) {
                const float* np0 = enc + (size_t)j0 * DIM + lane * 8;
                const float* np1 = enc + (size_t)j1 * DIM + lane * 8;
                e0 = ldcs4(np0); e1 = ldcs4(np0 + 4);
                f0 = ldcs4(np1); f1 = ldcs4(np1 + 4);
            }
            // fetch indices for pair (i+4) (used next iteration)
            if (i + 4 < cnt) {
                j0 = g_sorted[start + i + 4];
                j1 = g_sorted[start + ((i + 5 < cnt) ? i + 5 : i + 4)];
            }

            float p = ge0.x * q0.x + ge0.y * q0.y + ge0.z * q0.z + ge0.w * q0.w
                    + ge1.x * q1.x + ge1.y * q1.y + ge1.z * q1.z + ge1.w * q1.w;
            float s = gf0.x * q0.x + gf0.y * q0.y + gf0.z * q0.z + gf0.w * q0.w
                    + gf1.x * q1.x + gf1.y * q1.y + gf1.z * q1.z + gf1.w * q1.w;
#pragma unroll
            for (int o = 16; o; o >>= 1) {
                p += __shfl_xor_sync(0xffffffffu, p, o);
                s += __shfl_xor_sync(0xffffffffu, s, o);
            }
            float w1 = __expf(p * 0.0625f);
            float w2 = (i + 1 < cnt) ? __expf(s * 0.0625f) : 0.0f;

            a0.x += w1 * ge0.x + w2 * gf0.x;
            a0.y += w1 * ge0.y + w2 * gf0.y;
            a0.z += w1 * ge0.z + w2 * gf0.z;
            a0.w += w1 * ge0.w + w2 * gf0.w;
            a1.x += w1 * ge1.x + w2 * gf1.x;
            a1.y += w1 * ge1.y + w2 * gf1.y;
            a1.z += w1 * ge1.z + w2 * gf1.z;
            a1.w += w1 * ge1.w + w2 * gf1.w;
            den += w1 + w2;
        }
    }

    float* op = g_agg + (size_t)node * DIM + lane * 8;
    *(float4*)op       = a0;
    *(float4*)(op + 4) = a1;
    if (lane == 0) g_denom[node] = den;
}

// ---------------------------------------------------------------------------
// TF32 tensor-core GEMM with fragment-swizzled SMEM (vector LDS).
//   MODE 0: KTOT=256, C = fp32 q projection.
//   MODE 1: KTOT=512, A2 scaled by 1/(denom+1e-9) on load, fused gate epilogue.
// Block tile 128x128, K-chunk 32, 256 threads = 8 warps (4M x 2N),
// warp tile 32x64 = 2x8 m16n8k8 mma tiles.
// ---------------------------------------------------------------------------
__device__ __forceinline__ unsigned cvt_tf32(float x) {
    unsigned u;
    asm("cvt.rna.tf32.f32 %0, %1;" : "=r"(u) : "f"(x));
    return u;
}

template <int KTOT, int MODE>
__global__ __launch_bounds__(256, 2)
void tf32_gemm_kernel(const float* __restrict__ A1,
                      const float* __restrict__ A2,
                      const float* __restrict__ W,
                      const float* __restrict__ bias,
                      float* __restrict__ Cout,
                      int M) {
    __shared__ uint4 AsF[8][4][33];
    __shared__ uint2 BsF[4][16][33];

    const int tid  = threadIdx.x;
    const int bm   = blockIdx.x * 128;
    const int bn   = blockIdx.y * 128;
    const int warp = tid >> 5;
    const int lane = tid & 31;
    const int g0   = (warp & 3) * 2;
    const int n80  = (warp >> 2) * 8;
    const int kq   = lane & 3;
    const int r    = lane >> 2;

    float c[2][8][4];
#pragma unroll
    for (int i = 0; i < 2; i++)
#pragma unroll
        for (int j = 0; j < 8; j++)
#pragma unroll
            for (int t = 0; t < 4; t++) c[i][j][t] = 0.0f;

    for (int k0 = 0; k0 < KTOT; k0 += 32) {
        const bool isA2 = (KTOT == 512) && (k0 >= 256);
        const float* Asrc = isA2 ? A2 : A1;
        const int kloc = k0 & 255;

#pragma unroll
        for (int j = 0; j < 4; j++) {
            int i = tid + j * 256;
            int row = i >> 3;
            int c4  = i & 7;
            int grow = bm + row; if (grow >= M) grow = M - 1;
            float4 v = *(const float4*)(Asrc + (size_t)grow * 256 + kloc + c4 * 4);
            if (MODE == 1 && isA2) {
                float rd = 1.0f / (g_denom[grow] + 1e-9f);
                v.x *= rd; v.y *= rd; v.z *= rd; v.w *= rd;
            }
            int gg = row >> 4, h = (row >> 3) & 1, rr = row & 7;
            int kk = c4 >> 1, half = c4 & 1;
            unsigned* dst = (unsigned*)&AsF[gg][kk][0];
            int base = rr * 16 + half * 2 + h;
            dst[base]      = cvt_tf32(v.x);
            dst[base + 4]  = cvt_tf32(v.y);
            dst[base + 8]  = cvt_tf32(v.z);
            dst[base + 12] = cvt_tf32(v.w);
        }
#pragma unroll
        for (int j = 0; j < 4; j++) {
            int i = tid + j * 256;
            int krow = i >> 5;
            int c4   = i & 31;
            float4 v = *(const float4*)(W + (size_t)(k0 + krow) * 256 + bn + c4 * 4);
            int kk = krow >> 3, kqw = krow & 3, half = (krow >> 2) & 1;
            int n8 = c4 >> 1, rb = (c4 & 1) * 4;
            unsigned* dst = (unsigned*)&BsF[kk][n8][0];
            int base = (rb * 4 + kqw) * 2 + half;
            dst[base]      = cvt_tf32(v.x);
            dst[base + 8]  = cvt_tf32(v.y);
            dst[base + 16] = cvt_tf32(v.z);
            dst[base + 24] = cvt_tf32(v.w);
        }
        __syncthreads();

#pragma unroll
        for (int kk = 0; kk < 4; kk++) {
            uint4 af[2];
            af[0] = AsF[g0][kk][lane];
            af[1] = AsF[g0 + 1][kk][lane];
            uint2 bf[8];
#pragma unroll
            for (int nt = 0; nt < 8; nt++) bf[nt] = BsF[kk][n80 + nt][lane];
#pragma unroll
            for (int mt = 0; mt < 2; mt++)
#pragma unroll
                for (int nt = 0; nt < 8; nt++) {
                    asm volatile(
                        "mma.sync.aligned.m16n8k8.row.col.f32.tf32.tf32.f32 "
                        "{%0,%1,%2,%3}, {%4,%5,%6,%7}, {%8,%9}, {%0,%1,%2,%3};"
                        : "+f"(c[mt][nt][0]), "+f"(c[mt][nt][1]),
                          "+f"(c[mt][nt][2]), "+f"(c[mt][nt][3])
                        : "r"(af[mt].x), "r"(af[mt].y), "r"(af[mt].z), "r"(af[mt].w),
                          "r"(bf[nt].x), "r"(bf[nt].y));
                }
        }
        __syncthreads();
    }

    const int wm = (warp & 3) * 32;
    const int wn = (warp >> 2) * 64;
#pragma unroll
    for (int mt = 0; mt < 2; mt++) {
#pragma unroll
        for (int h = 0; h < 2; h++) {
            int m = bm + wm + mt * 16 + r + h * 8;
            if (m >= M) continue;
            float rdm = 0.0f;
            if (MODE == 1) rdm = 1.0f / (g_denom[m] + 1e-9f);
#pragma unroll
            for (int nt = 0; nt < 8; nt++) {
                int n = bn + wn + nt * 8 + 2 * kq;
                float v0 = c[mt][nt][h * 2 + 0];
                float v1 = c[mt][nt][h * 2 + 1];
                if (MODE == 0) {
                    *(float2*)(Cout + (size_t)m * 256 + n) = make_float2(v0, v1);
                } else {
                    float2 bb = *(const float2*)(bias + n);
                    float2 pv = *(const float2*)(A1 + (size_t)m * 256 + n);
                    float2 ag = *(const float2*)(A2 + (size_t)m * 256 + n);
                    ag.x *= rdm; ag.y *= rdm;
                    float z0 = 1.0f / (1.0f + __expf(-(v0 + bb.x)));
                    float z1 = 1.0f / (1.0f + __expf(-(v1 + bb.y)));
                    float2 o;
                    o.x = z0 * pv.x + (1.0f - z0) * ag.x;
                    o.y = z1 * pv.y + (1.0f - z1) * ag.y;
                    *(float2*)(Cout + (size_t)m * 256 + n) = o;
                }
            }
        }
    }
}

// ---------------------------------------------------------------------------
// Launch
// Inputs: 0 encoded_paths f32 [2048,256,256], 1 paths_mask (autodetected),
// 2 paths_node_indices i32, 3 previous_encodings f32 [50000,256],
// 4 Wq f32 [256,256], 5 Wg f32 [512,256], 6 bg f32 [256], 7 nr_cfg_nodes
// ---------------------------------------------------------------------------
extern "C" void kernel_launch(void* const* d_in, const int* in_sizes, int n_in,
                              void* d_out, int out_size) {
    const float* enc  = (const float*)d_in[0];
    const void*  mask = d_in[1];
    const int*   idx  = (const int*)d_in[2];
    const float* prev = (const float*)d_in[3];
    const float* Wq   = (const float*)d_in[4];
    const float* Wg   = (const float*)d_in[5];
    const float* bg   = (const float*)d_in[6];
    float* out        = (float*)d_out;

    void *qp = nullptr, *aggp = nullptr;
    cudaGetSymbolAddress(&qp, g_q);
    cudaGetSymbolAddress(&aggp, g_agg);
    float* q_buf   = (float*)qp;
    float* agg_buf = (float*)aggp;

    const int M = NNODES;
    dim3 grid((M + 127) / 128, 2);

    // 0) detect mask element width; zero histogram
    detect_mask_kernel<<<1, 256>>>((const unsigned char*)mask);
    zero_hist_kernel<<<(NNODES + 255) / 256, 256>>>();

    // 1) q = prev @ Wq  (tf32 tensor cores)
    tf32_gemm_kernel<256, 0><<<grid, 256>>>(prev, prev, Wq, nullptr, q_buf, M);

    // 2) counting sort of live occurrences by node
    hist_kernel<<<PL_TOTAL / 256, 256>>>(mask, idx);
    scan_kernel<<<1, 1024>>>();
    fill_kernel<<<PL_TOTAL / 256, 256>>>(mask, idx);

    // 3) binned aggregation (one warp per node, 2-wide ILP + idx pipeline)
    agg_kernel<<<(NNODES * 32 + 255) / 256, 256>>>(enc);

    // 4) fused: out = z*prev + (1-z)*(agg/denom), z = sigmoid([prev|agg/denom]@Wg+bg)
    tf32_gemm_kernel<512, 1><<<grid, 256>>>(prev, agg_buf, Wg, bg, out, M);
}

// round 11
// speedup vs baseline: 1.2424x; 1.0402x over previous
#include <cuda_runtime.h>
#include <cuda_bf16.h>

#define PL_TOTAL (2048 * 256)   // 524288 occurrences
#define NNODES   50000
#define DIM      256

// Scratch (static device globals -- no allocation in kernel_launch)
__device__ __align__(32) float g_q[(size_t)NNODES * DIM];
__device__ __align__(16) float g_agg[(size_t)NNODES * DIM];
__device__ float g_denom[NNODES];
__device__ int   g_hist[NNODES];
__device__ int   g_start[NNODES];
__device__ int   g_cursor[NNODES];
__device__ int   g_sorted[PL_TOTAL];
__device__ int   g_mask_word;   // 1 = mask elements are 4-byte (f32/i32), 0 = 1-byte

__device__ __forceinline__ bool is_live(const void* mask, int occ) {
    return g_mask_word ? (((const unsigned*)mask)[occ] != 0u)
                       : (((const unsigned char*)mask)[occ] != 0);
}

// ---------------------------------------------------------------------------
// Detect mask element width from raw bytes (deterministic).
// ---------------------------------------------------------------------------
__global__ void detect_mask_kernel(const unsigned char* __restrict__ m) {
    __shared__ int f32flag, oddflag;
    if (threadIdx.x == 0) { f32flag = 0; oddflag = 0; }
    __syncthreads();
    for (int i = threadIdx.x; i < 4096; i += blockDim.x) {
        unsigned char b = m[i];
        if (b == 0x3F && (i & 3) == 3) atomicOr(&f32flag, 1);
        if (b != 0 && (i & 3) != 0)    atomicOr(&oddflag, 1);
    }
    __syncthreads();
    if (threadIdx.x == 0)
        g_mask_word = (f32flag || !oddflag) ? 1 : 0;
}

// ---------------------------------------------------------------------------
// Counting sort of live occurrences by node: hist -> scan -> fill
// ---------------------------------------------------------------------------
__global__ void zero_hist_kernel() {
    int i = blockIdx.x * blockDim.x + threadIdx.x;
    if (i < NNODES) g_hist[i] = 0;
}

__global__ __launch_bounds__(256)
void hist_kernel(const void* __restrict__ mask, const int* __restrict__ idx) {
    int occ = blockIdx.x * blockDim.x + threadIdx.x;
    if (occ >= PL_TOTAL) return;
    if (!is_live(mask, occ)) return;
    atomicAdd(&g_hist[idx[occ]], 1);
}

__global__ __launch_bounds__(1024)
void scan_kernel() {
    __shared__ int psum[1024];
    const int t = threadIdx.x;
    const int lo = t * 49;
    const int hi = min(lo + 49, NNODES);
    int s = 0;
    for (int i = lo; i < hi; i++) s += g_hist[i];
    psum[t] = s;
    __syncthreads();
    for (int d = 1; d < 1024; d <<= 1) {
        int v = (t >= d) ? psum[t - d] : 0;
        __syncthreads();
        psum[t] += v;
        __syncthreads();
    }
    int run = (t == 0) ? 0 : psum[t - 1];
    for (int i = lo; i < hi; i++) {
        g_start[i]  = run;
        g_cursor[i] = run;
        run += g_hist[i];
    }
}

__global__ __launch_bounds__(256)
void fill_kernel(const void* __restrict__ mask, const int* __restrict__ idx) {
    int occ = blockIdx.x * blockDim.x + threadIdx.x;
    if (occ >= PL_TOTAL) return;
    if (!is_live(mask, occ)) return;
    int pos = atomicAdd(&g_cursor[idx[occ]], 1);
    g_sorted[pos] = occ;
}

// ---------------------------------------------------------------------------
// Binned aggregation, 2-wide ILP (R7-exact, best measured): one warp per
// node, two occurrences per iteration as independent chains, next pair's
// loads issued before current pair's math. No atomics.
// ---------------------------------------------------------------------------
__device__ __forceinline__ float4 ldcs4(const float* p) {
    float4 v;
    asm volatile("ld.global.cs.v4.f32 {%0,%1,%2,%3}, [%4];"
                 : "=f"(v.x), "=f"(v.y), "=f"(v.z), "=f"(v.w) : "l"(p));
    return v;
}

__global__ __launch_bounds__(256)
void agg_kernel(const float* __restrict__ enc) {
    int node = (int)((blockIdx.x * blockDim.x + threadIdx.x) >> 5);
    int lane = threadIdx.x & 31;
    if (node >= NNODES) return;

    const int start = g_start[node];
    const int cnt   = g_hist[node];

    const float* qp = g_q + (size_t)node * DIM + lane * 8;
    float4 q0 = *(const float4*)qp;
    float4 q1 = *(const float4*)(qp + 4);

    float4 a0 = make_float4(0.f, 0.f, 0.f, 0.f);
    float4 a1 = make_float4(0.f, 0.f, 0.f, 0.f);
    float den = 0.0f;

    if (cnt > 0) {
        int o0 = g_sorted[start];
        int o1 = g_sorted[start + ((cnt > 1) ? 1 : 0)];
        const float* p0 = enc + (size_t)o0 * DIM + lane * 8;
        const float* p1 = enc + (size_t)o1 * DIM + lane * 8;
        float4 e0 = ldcs4(p0), e1 = ldcs4(p0 + 4);
        float4 f0 = ldcs4(p1), f1 = ldcs4(p1 + 4);

        for (int i = 0; i < cnt; i += 2) {
            float4 ge0 = e0, ge1 = e1, gf0 = f0, gf1 = f1;
            if (i + 2 < cnt) {   // prefetch next pair
                int n0 = g_sorted[start + i + 2];
                int n1 = g_sorted[start + ((i + 3 < cnt) ? i + 3 : i + 2)];
                const float* np0 = enc + (size_t)n0 * DIM + lane * 8;
                const float* np1 = enc + (size_t)n1 * DIM + lane * 8;
                e0 = ldcs4(np0); e1 = ldcs4(np0 + 4);
                f0 = ldcs4(np1); f1 = ldcs4(np1 + 4);
            }
            float p = ge0.x * q0.x + ge0.y * q0.y + ge0.z * q0.z + ge0.w * q0.w
                    + ge1.x * q1.x + ge1.y * q1.y + ge1.z * q1.z + ge1.w * q1.w;
            float s = gf0.x * q0.x + gf0.y * q0.y + gf0.z * q0.z + gf0.w * q0.w
                    + gf1.x * q1.x + gf1.y * q1.y + gf1.z * q1.z + gf1.w * q1.w;
#pragma unroll
            for (int o = 16; o; o >>= 1) {
                p += __shfl_xor_sync(0xffffffffu, p, o);
                s += __shfl_xor_sync(0xffffffffu, s, o);
            }
            float w1 = __expf(p * 0.0625f);
            float w2 = (i + 1 < cnt) ? __expf(s * 0.0625f) : 0.0f;

            a0.x += w1 * ge0.x + w2 * gf0.x;
            a0.y += w1 * ge0.y + w2 * gf0.y;
            a0.z += w1 * ge0.z + w2 * gf0.z;
            a0.w += w1 * ge0.w + w2 * gf0.w;
            a1.x += w1 * ge1.x + w2 * gf1.x;
            a1.y += w1 * ge1.y + w2 * gf1.y;
            a1.z += w1 * ge1.z + w2 * gf1.z;
            a1.w += w1 * ge1.w + w2 * gf1.w;
            den += w1 + w2;
        }
    }

    float* op = g_agg + (size_t)node * DIM + lane * 8;
    *(float4*)op       = a0;
    *(float4*)(op + 4) = a1;
    if (lane == 0) g_denom[node] = den;
}

// ---------------------------------------------------------------------------
// TF32 tensor-core GEMM, fragment-swizzled dynamic SMEM, K-chunk 64:
// half the __syncthreads of the 32-chunk version, 16 LDG.128 in flight per
// thread during the load phase. 2 blocks/SM at 66KB dynamic SMEM each.
//   MODE 0: KTOT=256, C = fp32 q projection.
//   MODE 1: KTOT=512, A2 scaled by 1/(denom+1e-9) on load, fused gate epilogue.
// Block tile 128x128, 256 threads = 8 warps (4M x 2N), warp tile 32x64.
// ---------------------------------------------------------------------------
__device__ __forceinline__ unsigned cvt_tf32(float x) {
    unsigned u;
    asm("cvt.rna.tf32.f32 %0, %1;" : "=r"(u) : "f"(x));
    return u;
}

#define GEMM_SMEM_BYTES (8 * 8 * 33 * 16 + 8 * 16 * 33 * 8)   // 67584

template <int KTOT, int MODE>
__global__ __launch_bounds__(256, 2)
void tf32_gemm_kernel(const float* __restrict__ A1,
                      const float* __restrict__ A2,
                      const float* __restrict__ W,
                      const float* __restrict__ bias,
                      float* __restrict__ Cout,
                      int M) {
    extern __shared__ unsigned char smraw[];
    // AsF[g 0..7][kk 0..7][lane]: uint4 A fragment for m16 group g, k8 step kk
    // BsF[kk 0..7][n8 0..15][lane]: uint2 B fragment
    uint4 (*AsF)[8][33] = (uint4 (*)[8][33])smraw;
    uint2 (*BsF)[16][33] = (uint2 (*)[16][33])(smraw + 8 * 8 * 33 * 16);

    const int tid  = threadIdx.x;
    const int bm   = blockIdx.x * 128;
    const int bn   = blockIdx.y * 128;
    const int warp = tid >> 5;
    const int lane = tid & 31;
    const int g0   = (warp & 3) * 2;
    const int n80  = (warp >> 2) * 8;
    const int kq   = lane & 3;
    const int r    = lane >> 2;

    float c[2][8][4];
#pragma unroll
    for (int i = 0; i < 2; i++)
#pragma unroll
        for (int j = 0; j < 8; j++)
#pragma unroll
            for (int t = 0; t < 4; t++) c[i][j][t] = 0.0f;

    for (int k0 = 0; k0 < KTOT; k0 += 64) {
        const bool isA2 = (KTOT == 512) && (k0 >= 256);
        const float* Asrc = isA2 ? A2 : A1;
        const int kloc = k0 & 255;

        // --- A tile: 128 rows x 64 cols = 2048 float4, 8 per thread ---
#pragma unroll
        for (int j = 0; j < 8; j++) {
            int i = tid + j * 256;          // 0..2047
            int row = i >> 4;               // 0..127
            int c4  = i & 15;               // 0..15
            int grow = bm + row; if (grow >= M) grow = M - 1;
            float4 v = *(const float4*)(Asrc + (size_t)grow * 256 + kloc + c4 * 4);
            if (MODE == 1 && isA2) {
                float rd = 1.0f / (g_denom[grow] + 1e-9f);
                v.x *= rd; v.y *= rd; v.z *= rd; v.w *= rd;
            }
            int gg = row >> 4, h = (row >> 3) & 1, rr = row & 7;
            int kk = c4 >> 1, half = c4 & 1;
            unsigned* dst = (unsigned*)&AsF[gg][kk][0];
            int base = rr * 16 + half * 2 + h;
            dst[base]      = cvt_tf32(v.x);
            dst[base + 4]  = cvt_tf32(v.y);
            dst[base + 8]  = cvt_tf32(v.z);
            dst[base + 12] = cvt_tf32(v.w);
        }
        // --- B tile: 64 rows x 128 cols = 2048 float4, 8 per thread ---
#pragma unroll
        for (int j = 0; j < 8; j++) {
            int i = tid + j * 256;
            int krow = i >> 5;              // 0..63
            int c4   = i & 31;              // 0..31
            float4 v = *(const float4*)(W + (size_t)(k0 + krow) * 256 + bn + c4 * 4);
            int kk = krow >> 3, kqw = krow & 3, half = (krow >> 2) & 1;
            int n8 = c4 >> 1, rb = (c4 & 1) * 4;
            unsigned* dst = (unsigned*)&BsF[kk][n8][0];
            int base = (rb * 4 + kqw) * 2 + half;
            dst[base]      = cvt_tf32(v.x);
            dst[base + 8]  = cvt_tf32(v.y);
            dst[base + 16] = cvt_tf32(v.z);
            dst[base + 24] = cvt_tf32(v.w);
        }
        __syncthreads();

#pragma unroll
        for (int kk = 0; kk < 8; kk++) {
            uint4 af[2];
            af[0] = AsF[g0][kk][lane];
            af[1] = AsF[g0 + 1][kk][lane];
            uint2 bf[8];
#pragma unroll
            for (int nt = 0; nt < 8; nt++) bf[nt] = BsF[kk][n80 + nt][lane];
#pragma unroll
            for (int mt = 0; mt < 2; mt++)
#pragma unroll
                for (int nt = 0; nt < 8; nt++) {
                    asm volatile(
                        "mma.sync.aligned.m16n8k8.row.col.f32.tf32.tf32.f32 "
                        "{%0,%1,%2,%3}, {%4,%5,%6,%7}, {%8,%9}, {%0,%1,%2,%3};"
                        : "+f"(c[mt][nt][0]), "+f"(c[mt][nt][1]),
                          "+f"(c[mt][nt][2]), "+f"(c[mt][nt][3])
                        : "r"(af[mt].x), "r"(af[mt].y), "r"(af[mt].z), "r"(af[mt].w),
                          "r"(bf[nt].x), "r"(bf[nt].y));
                }
        }
        __syncthreads();
    }

    const int wm = (warp & 3) * 32;
    const int wn = (warp >> 2) * 64;
#pragma unroll
    for (int mt = 0; mt < 2; mt++) {
#pragma unroll
        for (int h = 0; h < 2; h++) {
            int m = bm + wm + mt * 16 + r + h * 8;
            if (m >= M) continue;
            float rdm = 0.0f;
            if (MODE == 1) rdm = 1.0f / (g_denom[m] + 1e-9f);
#pragma unroll
            for (int nt = 0; nt < 8; nt++) {
                int n = bn + wn + nt * 8 + 2 * kq;
                float v0 = c[mt][nt][h * 2 + 0];
                float v1 = c[mt][nt][h * 2 + 1];
                if (MODE == 0) {
                    *(float2*)(Cout + (size_t)m * 256 + n) = make_float2(v0, v1);
                } else {
                    float2 bb = *(const float2*)(bias + n);
                    float2 pv = *(const float2*)(A1 + (size_t)m * 256 + n);
                    float2 ag = *(const float2*)(A2 + (size_t)m * 256 + n);
                    ag.x *= rdm; ag.y *= rdm;
                    float z0 = 1.0f / (1.0f + __expf(-(v0 + bb.x)));
                    float z1 = 1.0f / (1.0f + __expf(-(v1 + bb.y)));
                    float2 o;
                    o.x = z0 * pv.x + (1.0f - z0) * ag.x;
                    o.y = z1 * pv.y + (1.0f - z1) * ag.y;
                    *(float2*)(Cout + (size_t)m * 256 + n) = o;
                }
            }
        }
    }
}

// ---------------------------------------------------------------------------
// Launch
// Inputs: 0 encoded_paths f32 [2048,256,256], 1 paths_mask (autodetected),
// 2 paths_node_indices i32, 3 previous_encodings f32 [50000,256],
// 4 Wq f32 [256,256], 5 Wg f32 [512,256], 6 bg f32 [256], 7 nr_cfg_nodes
// ---------------------------------------------------------------------------
extern "C" void kernel_launch(void* const* d_in, const int* in_sizes, int n_in,
                              void* d_out, int out_size) {
    const float* enc  = (const float*)d_in[0];
    const void*  mask = d_in[1];
    const int*   idx  = (const int*)d_in[2];
    const float* prev = (const float*)d_in[3];
    const float* Wq   = (const float*)d_in[4];
    const float* Wg   = (const float*)d_in[5];
    const float* bg   = (const float*)d_in[6];
    float* out        = (float*)d_out;

    void *qp = nullptr, *aggp = nullptr;
    cudaGetSymbolAddress(&qp, g_q);
    cudaGetSymbolAddress(&aggp, g_agg);
    float* q_buf   = (float*)qp;
    float* agg_buf = (float*)aggp;

    const int M = NNODES;
    dim3 grid((M + 127) / 128, 2);

    // opt in to 66KB dynamic SMEM (host-side attribute set; capture-legal)
    cudaFuncSetAttribute(tf32_gemm_kernel<256, 0>,
                         cudaFuncAttributeMaxDynamicSharedMemorySize,
                         GEMM_SMEM_BYTES);
    cudaFuncSetAttribute(tf32_gemm_kernel<512, 1>,
                         cudaFuncAttributeMaxDynamicSharedMemorySize,
                         GEMM_SMEM_BYTES);

    // 0) detect mask element width; zero histogram
    detect_mask_kernel<<<1, 256>>>((const unsigned char*)mask);
    zero_hist_kernel<<<(NNODES + 255) / 256, 256>>>();

    // 1) q = prev @ Wq  (tf32 tensor cores)
    tf32_gemm_kernel<256, 0><<<grid, 256, GEMM_SMEM_BYTES>>>(
        prev, prev, Wq, nullptr, q_buf, M);

    // 2) counting sort of live occurrences by node
    hist_kernel<<<PL_TOTAL / 256, 256>>>(mask, idx);
    scan_kernel<<<1, 1024>>>();
    fill_kernel<<<PL_TOTAL / 256, 256>>>(mask, idx);

    // 3) binned aggregation (one warp per node, 2-wide ILP, no atomics)
    agg_kernel<<<(NNODES * 32 + 255) / 256, 256>>>(enc);

    // 4) fused: out = z*prev + (1-z)*(agg/denom), z = sigmoid([prev|agg/denom]@Wg+bg)
    tf32_gemm_kernel<512, 1><<<grid, 256, GEMM_SMEM_BYTES>>>(
        prev, agg_buf, Wg, bg, out, M);
}